// round 7
// baseline (speedup 1.0000x reference)
#include <cuda_runtime.h>
#include <math.h>
#include <stdint.h>

#define T_TOK 32768
#define DIM   128
#define KC    8192
#define BM    128
#define NT    64
#define ITERS (KC / NT)          /* 128 */
#define GRID_GEMM (T_TOK / BM)   /* 256 */
#define TILE_BYTES 8192
#define SMEM_GEMM (2 * TILE_BYTES)
#define PAD 132
#define SMEM_PROJ (2 * 128 * PAD * 4)

/* ---------------- device scratch (no allocations) ---------------- */
__device__ __align__(16) unsigned char g_cbt[ITERS * TILE_BYTES]; /* 1MB int8 B frags */
__device__ float  g_codebook[KC * DIM];
__device__ __align__(16) float  g_cnorm[KC];
__device__ __align__(16) float2 g_cns[KC];   /* {cnorm, SC_k = max|c_k|/127} */
__device__ int4   g_cand[T_TOK * 4];         /* 16 candidates per token (4 per cc lane) */
__device__ int    g_counts[KC];
__device__ double g_ssep[T_TOK / 8];

__device__ __forceinline__ uint32_t smem_u32(const void* p) {
    uint32_t a;
    asm("{ .reg .u64 t; cvta.to.shared.u64 t, %1; cvt.u32.u64 %0, t; }"
        : "=r"(a) : "l"(p));
    return a;
}

#define CP16(dst, src) \
    asm volatile("cp.async.cg.shared.global [%0], [%1], 16;" :: "r"((uint32_t)(dst)), "l"(src))
#define CP_COMMIT() asm volatile("cp.async.commit_group;" ::: "memory")
#define CP_WAIT0()  asm volatile("cp.async.wait_group 0;"  ::: "memory")

#define MMA_S8(d, a, b0, b1) \
    asm volatile("mma.sync.aligned.m16n8k32.row.col.s32.s8.s8.s32 " \
                 "{%0,%1,%2,%3}, {%4,%5,%6,%7}, {%8,%9}, {%0,%1,%2,%3};" \
                 : "+r"((d)[0]), "+r"((d)[1]), "+r"((d)[2]), "+r"((d)[3]) \
                 : "r"((a)[0]), "r"((a)[1]), "r"((a)[2]), "r"((a)[3]), \
                   "r"(b0), "r"(b1))

#define INS4(tv0, tv1, tv2, tv3, ti0, ti1, ti2, ti3, v, n) do {               \
    if ((v) < (tv3)) {                                                        \
        if ((v) < (tv2)) {                                                    \
            tv3 = tv2; ti3 = ti2;                                             \
            if ((v) < (tv1)) {                                                \
                tv2 = tv1; ti2 = ti1;                                         \
                if ((v) < (tv0)) { tv1 = tv0; ti1 = ti0; tv0 = (v); ti0 = (n); } \
                else             { tv1 = (v); ti1 = (n); }                    \
            } else { tv2 = (v); ti2 = (n); }                                  \
        } else { tv3 = (v); ti3 = (n); }                                      \
    }                                                                         \
} while (0)

__device__ __forceinline__ int qclamp(float v, float s) {
    int q = __float2int_rn(v * s);
    return max(-127, min(127, q));
}
__device__ __forceinline__ uint32_t q4pack(float4 v, float s) {
    int a = qclamp(v.x, s), b = qclamp(v.y, s), c = qclamp(v.z, s), d = qclamp(v.w, s);
    return (uint32_t)(a & 0xFF) | ((uint32_t)(b & 0xFF) << 8)
         | ((uint32_t)(c & 0xFF) << 16) | ((uint32_t)(d & 0xFF) << 24);
}

/* ---------------- zero counts ---------------- */
__global__ void k_init() {
    int i = blockIdx.x * blockDim.x + threadIdx.x;
    if (i < KC) g_counts[i] = 0;
}

/* ---------------- projection GEMM + int8 pack ----------------
   int8 B layout per 64-code tile (8KB): [nblk(8)][kblk(4)][lane(32)] x 8B,
   lane = nl*4 + kq; within 8B: reg(2) x byte(4);
   code n = tile*64 + nblk*8 + nl, k = kblk*32 + reg*16 + kq*4 + byte */
__global__ __launch_bounds__(256, 1)
void k_proj(const float* __restrict__ emb,
            const float* __restrict__ pw,
            const float* __restrict__ pbias) {
    extern __shared__ float ps[];
    float* es = ps;
    float* wsm = ps + 128 * PAD;
    const int tid = threadIdx.x;
    const int tx = tid & 15, ty = tid >> 4;
    const int c0 = blockIdx.x * 128;

#pragma unroll
    for (int i = 0; i < 16; i++) {
        int f = tid + i * 256;
        int row = f >> 5;
        int c4 = f & 31;
        int sw = (((row >> 2) ^ (c4 & 7)) << 2) | (row & 3);
        float4 v = *((const float4*)(emb + (size_t)(c0 + row) * DIM) + c4);
        es[(4 * c4 + 0) * PAD + sw] = v.x;
        es[(4 * c4 + 1) * PAD + sw] = v.y;
        es[(4 * c4 + 2) * PAD + sw] = v.z;
        es[(4 * c4 + 3) * PAD + sw] = v.w;
        float4 w = *((const float4*)(pw + (size_t)row * DIM) + c4);
        wsm[(4 * c4 + 0) * PAD + sw] = w.x;
        wsm[(4 * c4 + 1) * PAD + sw] = w.y;
        wsm[(4 * c4 + 2) * PAD + sw] = w.z;
        wsm[(4 * c4 + 3) * PAD + sw] = w.w;
    }
    __syncthreads();

    float acc[8][8];
#pragma unroll
    for (int im = 0; im < 8; im++)
#pragma unroll
        for (int jn = 0; jn < 8; jn++) acc[im][jn] = 0.0f;

#pragma unroll 4
    for (int k = 0; k < 128; k++) {
        int s = (k >> 2) & 7;
        const float* er = es + k * PAD;
        const float* wr = wsm + k * PAD;
        float4 a0 = *(const float4*)(er + ((ty ^ s) << 2));
        float4 a1 = *(const float4*)(er + 64 + ((ty ^ s) << 2));
        float4 b0 = *(const float4*)(wr + ((tx ^ s) << 2));
        float4 b1 = *(const float4*)(wr + 64 + ((tx ^ s) << 2));
        float a[8] = {a0.x, a0.y, a0.z, a0.w, a1.x, a1.y, a1.z, a1.w};
        float b[8] = {b0.x, b0.y, b0.z, b0.w, b1.x, b1.y, b1.z, b1.w};
#pragma unroll
        for (int im = 0; im < 8; im++)
#pragma unroll
            for (int jn = 0; jn < 8; jn++)
                acc[im][jn] = fmaf(a[im], b[jn], acc[im][jn]);
    }

    float cnp[8], mxp[8];
#pragma unroll
    for (int im = 0; im < 8; im++) { cnp[im] = 0.0f; mxp[im] = 0.0f; }

#pragma unroll
    for (int im = 0; im < 8; im++) {
        int cl = (im < 4) ? (ty * 4 + im) : (64 + ty * 4 + im - 4);
        int cg = c0 + cl;
#pragma unroll
        for (int jn = 0; jn < 8; jn++) {
            int d = (jn < 4) ? (tx * 4 + jn) : (64 + tx * 4 + jn - 4);
            float val = acc[im][jn] + pbias[d];
            acc[im][jn] = val;
            g_codebook[(size_t)cg * DIM + d] = val;
            cnp[im] = fmaf(val, val, cnp[im]);
            mxp[im] = fmaxf(mxp[im], fabsf(val));
        }
    }
#pragma unroll
    for (int im = 0; im < 8; im++) {
#pragma unroll
        for (int o = 8; o > 0; o >>= 1) {
            cnp[im] += __shfl_xor_sync(0xffffffffu, cnp[im], o, 16);
            mxp[im] = fmaxf(mxp[im], __shfl_xor_sync(0xffffffffu, mxp[im], o, 16));
        }
    }
#pragma unroll
    for (int im = 0; im < 8; im++) {
        int cl = (im < 4) ? (ty * 4 + im) : (64 + ty * 4 + im - 4);
        int cg = c0 + cl;
        float inv = 127.0f / mxp[im];
        int tile = cg >> 6, nblk = (cg >> 3) & 7, nl = cg & 7;
#pragma unroll
        for (int g = 0; g < 2; g++) {
            int d0 = g * 64 + tx * 4;
            int kblk = d0 >> 5, reg = (d0 >> 4) & 1, kq = (d0 >> 2) & 3;
            int lane = nl * 4 + kq;
            float4 v = make_float4(acc[im][g * 4 + 0], acc[im][g * 4 + 1],
                                   acc[im][g * 4 + 2], acc[im][g * 4 + 3]);
            uint32_t pk = q4pack(v, inv);
            size_t off = (size_t)tile * TILE_BYTES + nblk * 1024 + kblk * 256
                       + lane * 8 + reg * 4;
            *(uint32_t*)(g_cbt + off) = pk;
        }
        if (tx == 0) {
            g_cnorm[cg] = cnp[im];
            g_cns[cg] = make_float2(cnp[im], mxp[im] * (1.0f / 127.0f));
        }
    }
}

/* ---------------- fused int8 IMMA distance GEMM + per-lane top-4 ---------------- */
__global__ __launch_bounds__(256, 2)
void k_gemm(const float* __restrict__ z) {
    extern __shared__ unsigned char smem[];
    const uint32_t sb = smem_u32(smem);
    const int tid = threadIdx.x;
    const int lane = tid & 31;
    const int warp = tid >> 5;
    const int r = lane >> 2;
    const int cc = lane & 3;
    const int m0 = blockIdx.x * BM;

    /* prefetch B tile 0 (8KB: 2 x 16B per thread) */
#pragma unroll
    for (int j = 0; j < 2; j++) {
        uint32_t off = (uint32_t)(tid + j * 256) * 16;
        CP16(sb + off, g_cbt + off);
    }
    CP_COMMIT();

    /* A fragments with PER-TOKEN scale.
       This thread holds 32 elems of row r and 32 of row r+8. */
    uint32_t A[4][4];
    float f2a, f2b;
    {
        const float4* z0 = (const float4*)(z + (size_t)(m0 + warp * 16 + r) * DIM);
        const float4* z1 = (const float4*)(z + (size_t)(m0 + warp * 16 + r + 8) * DIM);
        float4 v0[8], v1[8];
#pragma unroll
        for (int kb = 0; kb < 4; kb++) {
            v0[kb * 2]     = z0[kb * 8 + cc];
            v0[kb * 2 + 1] = z0[kb * 8 + 4 + cc];
            v1[kb * 2]     = z1[kb * 8 + cc];
            v1[kb * 2 + 1] = z1[kb * 8 + 4 + cc];
        }
        float ma = 0.0f, mb = 0.0f;
#pragma unroll
        for (int i = 0; i < 8; i++) {
            ma = fmaxf(ma, fmaxf(fmaxf(fabsf(v0[i].x), fabsf(v0[i].y)),
                                 fmaxf(fabsf(v0[i].z), fabsf(v0[i].w))));
            mb = fmaxf(mb, fmaxf(fmaxf(fabsf(v1[i].x), fabsf(v1[i].y)),
                                 fmaxf(fabsf(v1[i].z), fabsf(v1[i].w))));
        }
#pragma unroll
        for (int o = 1; o <= 2; o <<= 1) {
            ma = fmaxf(ma, __shfl_xor_sync(0xffffffffu, ma, o));
            mb = fmaxf(mb, __shfl_xor_sync(0xffffffffu, mb, o));
        }
        float inva = 127.0f / ma, invb = 127.0f / mb;
#pragma unroll
        for (int kb = 0; kb < 4; kb++) {
            A[kb][0] = q4pack(v0[kb * 2], inva);
            A[kb][1] = q4pack(v1[kb * 2], invb);
            A[kb][2] = q4pack(v0[kb * 2 + 1], inva);
            A[kb][3] = q4pack(v1[kb * 2 + 1], invb);
        }
        f2a = 2.0f * ma * (1.0f / 127.0f);
        f2b = 2.0f * mb * (1.0f / 127.0f);
    }

    float av0 = 3.4e38f, av1 = 3.4e38f, av2 = 3.4e38f, av3 = 3.4e38f;
    float bv0 = 3.4e38f, bv1 = 3.4e38f, bv2 = 3.4e38f, bv3 = 3.4e38f;
    int ai0 = 0, ai1 = 0, ai2 = 0, ai3 = 0;
    int bi0 = 0, bi1 = 0, bi2 = 0, bi3 = 0;

    for (int i = 0; i < ITERS; i++) {
        CP_WAIT0();
        __syncthreads();
        if (i + 1 < ITERS) {
            const unsigned char* src = g_cbt + (size_t)(i + 1) * TILE_BYTES;
            uint32_t dst = sb + ((i + 1) & 1) * TILE_BYTES;
#pragma unroll
            for (int j = 0; j < 2; j++) {
                uint32_t off = (uint32_t)(tid + j * 256) * 16;
                CP16(dst + off, src + off);
            }
            CP_COMMIT();
        }

        int acc[8][4];
#pragma unroll
        for (int nb = 0; nb < 8; nb++)
#pragma unroll
            for (int q = 0; q < 4; q++) acc[nb][q] = 0;

        const uint32_t bbase = sb + (i & 1) * TILE_BYTES + lane * 8;
#pragma unroll
        for (int kb = 0; kb < 4; kb++) {
#pragma unroll
            for (int nb = 0; nb < 8; nb++) {
                uint32_t b0, b1;
                asm volatile("ld.shared.v2.b32 {%0,%1},[%2];"
                             : "=r"(b0), "=r"(b1) : "r"(bbase + nb * 1024 + kb * 256));
                MMA_S8(acc[nb], A[kb], b0, b1);
            }
        }

        const int n0i = i * 64;
#pragma unroll
        for (int nb = 0; nb < 8; nb++) {
            int n = n0i + nb * 8 + cc * 2;
            float4 cn = ((const float4*)g_cns)[n >> 1]; /* {cn_n, SC_n, cn_n1, SC_n1} */
            float t0 = cn.y * (float)acc[nb][0];
            float t1 = cn.w * (float)acc[nb][1];
            float t2 = cn.y * (float)acc[nb][2];
            float t3 = cn.w * (float)acc[nb][3];
            float s0 = fmaf(-f2a, t0, cn.x);
            float s1 = fmaf(-f2a, t1, cn.z);
            float s2 = fmaf(-f2b, t2, cn.x);
            float s3 = fmaf(-f2b, t3, cn.z);
            INS4(av0, av1, av2, av3, ai0, ai1, ai2, ai3, s0, n);
            INS4(av0, av1, av2, av3, ai0, ai1, ai2, ai3, s1, n + 1);
            INS4(bv0, bv1, bv2, bv3, bi0, bi1, bi2, bi3, s2, n);
            INS4(bv0, bv1, bv2, bv3, bi0, bi1, bi2, bi3, s3, n + 1);
        }
    }

    /* NO cross-lane merge: each cc lane stores its own top-4 (16 cands/token) */
    int tok = m0 + warp * 16 + r;
    g_cand[tok * 4 + cc]       = make_int4(ai0, ai1, ai2, ai3);
    g_cand[(tok + 8) * 4 + cc] = make_int4(bi0, bi1, bi2, bi3);
}

/* ---------------- exact fp32 rescore of 16 candidates + gather + loss ---------------- */
__global__ __launch_bounds__(256)
void k_rescore(const float* __restrict__ z, float* __restrict__ out) {
    __shared__ float wsq[8];
    const int lane = threadIdx.x & 31;
    const int warp = threadIdx.x >> 5;
    const int t = blockIdx.x * 8 + warp;

    /* candidate j = lane>>1 (16 cands); half = lane&1 covers 64 dims */
    const int* ci = (const int*)(g_cand + (size_t)t * 4);
    int cj = ci[lane >> 1];
    int half = lane & 1;
    const float4* zt = (const float4*)(z + (size_t)t * DIM) + half * 16;
    const float4* cb = (const float4*)(g_codebook + (size_t)cj * DIM) + half * 16;
    float d = 0.0f;
#pragma unroll
    for (int i = 0; i < 16; i++) {
        float4 a = zt[i], b = cb[i];
        d = fmaf(a.x, b.x, d);
        d = fmaf(a.y, b.y, d);
        d = fmaf(a.z, b.z, d);
        d = fmaf(a.w, b.w, d);
    }
    d += __shfl_xor_sync(0xffffffffu, d, 1);
    float s = g_cnorm[cj] - 2.0f * d;

    /* warp argmin with tie -> lower index */
    float bv = s; int bidx = cj;
#pragma unroll
    for (int o = 16; o > 0; o >>= 1) {
        float ov = __shfl_xor_sync(0xffffffffu, bv, o);
        int   oi = __shfl_xor_sync(0xffffffffu, bidx, o);
        if (ov < bv || (ov == bv && oi < bidx)) { bv = ov; bidx = oi; }
    }

    float4 zv = ((const float4*)(z + (size_t)t * DIM))[lane];
    float4 c  = ((const float4*)(g_codebook + (size_t)bidx * DIM))[lane];
    float dx = c.x - zv.x, dy = c.y - zv.y, dz = c.z - zv.z, dw = c.w - zv.w;
    float4 o4;
    o4.x = zv.x + dx; o4.y = zv.y + dy; o4.z = zv.z + dz; o4.w = zv.w + dw;
    ((float4*)(out + (size_t)t * DIM))[lane] = o4;

    float sq = dx * dx + dy * dy + dz * dz + dw * dw;
#pragma unroll
    for (int o = 16; o > 0; o >>= 1) sq += __shfl_xor_sync(0xffffffffu, sq, o);
    if (lane == 0) {
        wsq[warp] = sq;
        atomicAdd(&g_counts[bidx], 1);
    }
    __syncthreads();
    if (threadIdx.x == 0) {
        double sd = 0.0;
#pragma unroll
        for (int i = 0; i < 8; i++) sd += (double)wsq[i];
        g_ssep[blockIdx.x] = sd;
    }
}

/* ---------------- finalize commit_loss + perplexity ---------------- */
__global__ void k_final(float* __restrict__ out) {
    __shared__ double wd[8];
    __shared__ float wf[8];
    double sd = 0.0;
    for (int j = threadIdx.x; j < T_TOK / 8; j += 256) sd += g_ssep[j];
    float s = 0.0f;
    const float invT = 1.0f / (float)T_TOK;
    for (int i = threadIdx.x; i < KC; i += 256) {
        float e = (float)g_counts[i] * invT;
        s += e * logf(e + 1e-8f);
    }
#pragma unroll
    for (int o = 16; o > 0; o >>= 1) {
        sd += __shfl_down_sync(0xffffffffu, sd, o);
        s  += __shfl_down_sync(0xffffffffu, s, o);
    }
    if ((threadIdx.x & 31) == 0) { wd[threadIdx.x >> 5] = sd; wf[threadIdx.x >> 5] = s; }
    __syncthreads();
    if (threadIdx.x == 0) {
        double td = 0.0; float tf = 0.0f;
#pragma unroll
        for (int i = 0; i < 8; i++) { td += wd[i]; tf += wf[i]; }
        double mse = td / (double)((size_t)T_TOK * DIM);
        out[(size_t)T_TOK * DIM]     = (float)(1.25 * mse);
        out[(size_t)T_TOK * DIM + 1] = expf(-tf);
    }
}

extern "C" void kernel_launch(void* const* d_in, const int* in_sizes, int n_in,
                              void* d_out, int out_size) {
    const float* z   = (const float*)d_in[0];
    const float* emb = (const float*)d_in[1];
    const float* pw  = (const float*)d_in[2];
    const float* pb  = (const float*)d_in[3];
    float* out = (float*)d_out;

    cudaFuncSetAttribute(k_proj, cudaFuncAttributeMaxDynamicSharedMemorySize, SMEM_PROJ);
    cudaFuncSetAttribute(k_gemm, cudaFuncAttributeMaxDynamicSharedMemorySize, SMEM_GEMM);

    k_init<<<KC / 256, 256>>>();
    k_proj<<<KC / 128, 256, SMEM_PROJ>>>(emb, pw, pb);
    k_gemm<<<GRID_GEMM, 256, SMEM_GEMM>>>(z);
    k_rescore<<<T_TOK / 8, 256>>>(z, out);
    k_final<<<1, 256>>>(out);
}

// round 8
// speedup vs baseline: 2.0607x; 2.0607x over previous
#include <cuda_runtime.h>
#include <cuda_fp16.h>
#include <math.h>
#include <stdint.h>

#define T_TOK 32768
#define DIM   128
#define KC    8192
#define BM    128
#define NT    64
#define ITERS (KC / NT)          /* 128 */
#define GRID_GEMM (T_TOK / BM)   /* 256 */
#define TILE_BYTES 16384
#define SO_CNS (2 * TILE_BYTES)          /* cnorm region offset in smem */
#define SMEM_GEMM (2 * TILE_BYTES + KC * 4)  /* 64KB */
#define PAD 132
#define SMEM_PROJ (2 * 128 * PAD * 4)

/* ---------------- device scratch (no allocations) ---------------- */
__device__ __align__(16) unsigned char g_cbt[ITERS * TILE_BYTES]; /* 2MB fp16 B frags */
__device__ float  g_codebook[KC * DIM];
__device__ __align__(16) float g_cnorm[KC];
__device__ int4   g_cand[T_TOK];
__device__ int    g_counts[KC];
__device__ double g_ssep[T_TOK / 8];

__device__ __forceinline__ uint32_t smem_u32(const void* p) {
    uint32_t a;
    asm("{ .reg .u64 t; cvta.to.shared.u64 t, %1; cvt.u32.u64 %0, t; }"
        : "=r"(a) : "l"(p));
    return a;
}

#define CP16(dst, src) \
    asm volatile("cp.async.cg.shared.global [%0], [%1], 16;" :: "r"((uint32_t)(dst)), "l"(src))
#define CP_COMMIT() asm volatile("cp.async.commit_group;" ::: "memory")
#define CP_WAIT0()  asm volatile("cp.async.wait_group 0;"  ::: "memory")

#define MMA_F16(d, a, b0, b1) \
    asm volatile("mma.sync.aligned.m16n8k16.row.col.f32.f16.f16.f32 " \
                 "{%0,%1,%2,%3}, {%4,%5,%6,%7}, {%8,%9}, {%0,%1,%2,%3};" \
                 : "+f"((d)[0]), "+f"((d)[1]), "+f"((d)[2]), "+f"((d)[3]) \
                 : "r"((a)[0]), "r"((a)[1]), "r"((a)[2]), "r"((a)[3]), \
                   "r"(b0), "r"(b1))

#define INS4(tv0, tv1, tv2, tv3, ti0, ti1, ti2, ti3, v, n) do {               \
    if ((v) < (tv3)) {                                                        \
        if ((v) < (tv2)) {                                                    \
            tv3 = tv2; ti3 = ti2;                                             \
            if ((v) < (tv1)) {                                                \
                tv2 = tv1; ti2 = ti1;                                         \
                if ((v) < (tv0)) { tv1 = tv0; ti1 = ti0; tv0 = (v); ti0 = (n); } \
                else             { tv1 = (v); ti1 = (n); }                    \
            } else { tv2 = (v); ti2 = (n); }                                  \
        } else { tv3 = (v); ti3 = (n); }                                      \
    }                                                                         \
} while (0)

/* ---------------- zero counts ---------------- */
__global__ void k_init() {
    int i = blockIdx.x * blockDim.x + threadIdx.x;
    if (i < KC) g_counts[i] = 0;
}

/* ---------------- projection GEMM: C = emb @ W^T + b (128 codes/block, register tiled) ----------------
   Emits fp32 codebook, cnorm, fp16 packed B fragments.
   Packed layout per 64-code tile (16KB): [nblk(8)][kblk(8)][lane(32)] x 8B,
   8B = {h(k), h(k+1), h(k+8), h(k+9)}, lane = nl*4 + ksub,
   n = tile*64 + nblk*8 + nl, k = kblk*16 + regsel*8 + ksub*2 + par */
__global__ __launch_bounds__(256, 1)
void k_proj(const float* __restrict__ emb,
            const float* __restrict__ pw,
            const float* __restrict__ pbias) {
    extern __shared__ float ps[];
    float* es = ps;
    float* wsm = ps + 128 * PAD;
    const int tid = threadIdx.x;
    const int tx = tid & 15, ty = tid >> 4;
    const int c0 = blockIdx.x * 128;

#pragma unroll
    for (int i = 0; i < 16; i++) {
        int f = tid + i * 256;
        int row = f >> 5;
        int c4 = f & 31;
        int sw = (((row >> 2) ^ (c4 & 7)) << 2) | (row & 3);
        float4 v = *((const float4*)(emb + (size_t)(c0 + row) * DIM) + c4);
        es[(4 * c4 + 0) * PAD + sw] = v.x;
        es[(4 * c4 + 1) * PAD + sw] = v.y;
        es[(4 * c4 + 2) * PAD + sw] = v.z;
        es[(4 * c4 + 3) * PAD + sw] = v.w;
        float4 w = *((const float4*)(pw + (size_t)row * DIM) + c4);
        wsm[(4 * c4 + 0) * PAD + sw] = w.x;
        wsm[(4 * c4 + 1) * PAD + sw] = w.y;
        wsm[(4 * c4 + 2) * PAD + sw] = w.z;
        wsm[(4 * c4 + 3) * PAD + sw] = w.w;
    }
    __syncthreads();

    float acc[8][8];
#pragma unroll
    for (int im = 0; im < 8; im++)
#pragma unroll
        for (int jn = 0; jn < 8; jn++) acc[im][jn] = 0.0f;

#pragma unroll 4
    for (int k = 0; k < 128; k++) {
        int s = (k >> 2) & 7;
        const float* er = es + k * PAD;
        const float* wr = wsm + k * PAD;
        float4 a0 = *(const float4*)(er + ((ty ^ s) << 2));
        float4 a1 = *(const float4*)(er + 64 + ((ty ^ s) << 2));
        float4 b0 = *(const float4*)(wr + ((tx ^ s) << 2));
        float4 b1 = *(const float4*)(wr + 64 + ((tx ^ s) << 2));
        float a[8] = {a0.x, a0.y, a0.z, a0.w, a1.x, a1.y, a1.z, a1.w};
        float b[8] = {b0.x, b0.y, b0.z, b0.w, b1.x, b1.y, b1.z, b1.w};
#pragma unroll
        for (int im = 0; im < 8; im++)
#pragma unroll
            for (int jn = 0; jn < 8; jn++)
                acc[im][jn] = fmaf(a[im], b[jn], acc[im][jn]);
    }

    float cnp[8];
#pragma unroll
    for (int im = 0; im < 8; im++) cnp[im] = 0.0f;

#pragma unroll
    for (int im = 0; im < 8; im++) {
        int cl = (im < 4) ? (ty * 4 + im) : (64 + ty * 4 + im - 4);
        int cg = c0 + cl;
        int tile = cg >> 6, nblk = (cg >> 3) & 7, nl = cg & 7;
#pragma unroll
        for (int jn = 0; jn < 8; jn++) {
            int d = (jn < 4) ? (tx * 4 + jn) : (64 + tx * 4 + jn - 4);
            float val = acc[im][jn] + pbias[d];
            g_codebook[(size_t)cg * DIM + d] = val;
            cnp[im] = fmaf(val, val, cnp[im]);
            int kblk = d >> 4, kin = d & 15;
            int regsel = kin >> 3, ksub = (kin & 7) >> 1, par = kin & 1;
            int lane = nl * 4 + ksub;
            size_t off = (size_t)tile * TILE_BYTES + nblk * 2048 + kblk * 256
                       + lane * 8 + regsel * 4 + par * 2;
            *(__half*)(g_cbt + off) = __float2half_rn(val);
        }
    }
#pragma unroll
    for (int im = 0; im < 8; im++) {
#pragma unroll
        for (int o = 8; o > 0; o >>= 1)
            cnp[im] += __shfl_xor_sync(0xffffffffu, cnp[im], o, 16);
    }
    if (tx == 0) {
#pragma unroll
        for (int im = 0; im < 8; im++) {
            int cl = (im < 4) ? (ty * 4 + im) : (64 + ty * 4 + im - 4);
            g_cnorm[c0 + cl] = cnp[im];
        }
    }
}

/* ---------------- fused fp16 HMMA distance GEMM + top-4 argmin ---------------- */
__global__ __launch_bounds__(256, 2)
void k_gemm(const float* __restrict__ z) {
    extern __shared__ unsigned char smem[];
    const uint32_t sb = smem_u32(smem);
    const int tid = threadIdx.x;
    const int lane = tid & 31;
    const int warp = tid >> 5;
    const int r = lane >> 2;
    const int cc = lane & 3;
    const int m0 = blockIdx.x * BM;

    /* prefetch B tile 0 */
#pragma unroll
    for (int j = 0; j < 4; j++) {
        uint32_t off = (uint32_t)(tid + j * 256) * 16;
        CP16(sb + off, g_cbt + off);
    }
    CP_COMMIT();

    /* stage all cnorms into smem (32KB), overlapped with A-fragment build */
    {
        float4* dst = (float4*)(smem + SO_CNS);
        const float4* src = (const float4*)g_cnorm;
#pragma unroll
        for (int j = 0; j < 8; j++) dst[tid + j * 256] = src[tid + j * 256];
    }

    /* A fragments (fp16) in registers */
    uint32_t A[8][4];
    {
        const float* z0 = z + (size_t)(m0 + warp * 16 + r) * DIM;
#pragma unroll
        for (int kb = 0; kb < 8; kb++) {
#pragma unroll
            for (int q = 0; q < 4; q++) {
                const float* src = z0 + ((q & 1) ? 8 * DIM : 0) + kb * 16 + (q >> 1) * 8 + cc * 2;
                float2 v = *(const float2*)src;
                __half2 hh = __floats2half2_rn(v.x, v.y);
                A[kb][q] = *(uint32_t*)&hh;
            }
        }
    }
    const unsigned char* cns = smem + SO_CNS;

    float av0 = 3.4e38f, av1 = 3.4e38f, av2 = 3.4e38f, av3 = 3.4e38f;
    float bv0 = 3.4e38f, bv1 = 3.4e38f, bv2 = 3.4e38f, bv3 = 3.4e38f;
    int ai0 = 0, ai1 = 0, ai2 = 0, ai3 = 0;
    int bi0 = 0, bi1 = 0, bi2 = 0, bi3 = 0;

    for (int i = 0; i < ITERS; i++) {
        CP_WAIT0();
        __syncthreads();
        if (i + 1 < ITERS) {
            const unsigned char* src = g_cbt + (size_t)(i + 1) * TILE_BYTES;
            uint32_t dst = sb + ((i + 1) & 1) * TILE_BYTES;
#pragma unroll
            for (int j = 0; j < 4; j++) {
                uint32_t off = (uint32_t)(tid + j * 256) * 16;
                CP16(dst + off, src + off);
            }
            CP_COMMIT();
        }

        float acc[8][4];
#pragma unroll
        for (int nb = 0; nb < 8; nb++)
#pragma unroll
            for (int q = 0; q < 4; q++) acc[nb][q] = 0.0f;

        const uint32_t bbase = sb + (i & 1) * TILE_BYTES + lane * 8;
#pragma unroll
        for (int kb = 0; kb < 8; kb++) {
#pragma unroll
            for (int nb = 0; nb < 8; nb++) {
                uint32_t b0, b1;
                asm volatile("ld.shared.v2.b32 {%0,%1},[%2];"
                             : "=r"(b0), "=r"(b1) : "r"(bbase + nb * 2048 + kb * 256));
                MMA_F16(acc[nb], A[kb], b0, b1);
            }
        }

        const int n0i = i * 64;
#pragma unroll
        for (int nb = 0; nb < 8; nb++) {
            int n = n0i + nb * 8 + cc * 2;
            float2 cn = *(const float2*)(cns + (uint32_t)n * 4);
            float s0 = fmaf(-2.0f, acc[nb][0], cn.x);
            float s1 = fmaf(-2.0f, acc[nb][1], cn.y);
            float s2 = fmaf(-2.0f, acc[nb][2], cn.x);
            float s3 = fmaf(-2.0f, acc[nb][3], cn.y);
            INS4(av0, av1, av2, av3, ai0, ai1, ai2, ai3, s0, n);
            INS4(av0, av1, av2, av3, ai0, ai1, ai2, ai3, s1, n + 1);
            INS4(bv0, bv1, bv2, bv3, bi0, bi1, bi2, bi3, s2, n);
            INS4(bv0, bv1, bv2, bv3, bi0, bi1, bi2, bi3, s3, n + 1);
        }
    }

    /* merge top-4 across the 4 cc lanes */
#pragma unroll
    for (int off = 1; off <= 2; off <<= 1) {
        float wa0 = __shfl_xor_sync(0xffffffffu, av0, off);
        float wa1 = __shfl_xor_sync(0xffffffffu, av1, off);
        float wa2 = __shfl_xor_sync(0xffffffffu, av2, off);
        float wa3 = __shfl_xor_sync(0xffffffffu, av3, off);
        int ja0 = __shfl_xor_sync(0xffffffffu, ai0, off);
        int ja1 = __shfl_xor_sync(0xffffffffu, ai1, off);
        int ja2 = __shfl_xor_sync(0xffffffffu, ai2, off);
        int ja3 = __shfl_xor_sync(0xffffffffu, ai3, off);
        float wb0 = __shfl_xor_sync(0xffffffffu, bv0, off);
        float wb1 = __shfl_xor_sync(0xffffffffu, bv1, off);
        float wb2 = __shfl_xor_sync(0xffffffffu, bv2, off);
        float wb3 = __shfl_xor_sync(0xffffffffu, bv3, off);
        int jb0 = __shfl_xor_sync(0xffffffffu, bi0, off);
        int jb1 = __shfl_xor_sync(0xffffffffu, bi1, off);
        int jb2 = __shfl_xor_sync(0xffffffffu, bi2, off);
        int jb3 = __shfl_xor_sync(0xffffffffu, bi3, off);
        INS4(av0, av1, av2, av3, ai0, ai1, ai2, ai3, wa0, ja0);
        INS4(av0, av1, av2, av3, ai0, ai1, ai2, ai3, wa1, ja1);
        INS4(av0, av1, av2, av3, ai0, ai1, ai2, ai3, wa2, ja2);
        INS4(av0, av1, av2, av3, ai0, ai1, ai2, ai3, wa3, ja3);
        INS4(bv0, bv1, bv2, bv3, bi0, bi1, bi2, bi3, wb0, jb0);
        INS4(bv0, bv1, bv2, bv3, bi0, bi1, bi2, bi3, wb1, jb1);
        INS4(bv0, bv1, bv2, bv3, bi0, bi1, bi2, bi3, wb2, jb2);
        INS4(bv0, bv1, bv2, bv3, bi0, bi1, bi2, bi3, wb3, jb3);
    }
    if (cc == 0) {
        int tok = m0 + warp * 16 + r;
        g_cand[tok]     = make_int4(ai0, ai1, ai2, ai3);
        g_cand[tok + 8] = make_int4(bi0, bi1, bi2, bi3);
    }
}

/* ---------------- exact fp32 rescore of top-4 + gather + loss partials ---------------- */
__global__ __launch_bounds__(256)
void k_rescore(const float* __restrict__ z, float* __restrict__ out) {
    __shared__ float wsq[8];
    const int lane = threadIdx.x & 31;
    const int warp = threadIdx.x >> 5;
    const int t = blockIdx.x * 8 + warp;

    int4 cd = g_cand[t];
    float4 zv = ((const float4*)(z + (size_t)t * DIM))[lane];
    float4 c0 = ((const float4*)(g_codebook + (size_t)cd.x * DIM))[lane];
    float4 c1 = ((const float4*)(g_codebook + (size_t)cd.y * DIM))[lane];
    float4 c2 = ((const float4*)(g_codebook + (size_t)cd.z * DIM))[lane];
    float4 c3 = ((const float4*)(g_codebook + (size_t)cd.w * DIM))[lane];
    float d0 = zv.x * c0.x + zv.y * c0.y + zv.z * c0.z + zv.w * c0.w;
    float d1 = zv.x * c1.x + zv.y * c1.y + zv.z * c1.z + zv.w * c1.w;
    float d2 = zv.x * c2.x + zv.y * c2.y + zv.z * c2.z + zv.w * c2.w;
    float d3 = zv.x * c3.x + zv.y * c3.y + zv.z * c3.z + zv.w * c3.w;
#pragma unroll
    for (int o = 16; o > 0; o >>= 1) {
        d0 += __shfl_xor_sync(0xffffffffu, d0, o);
        d1 += __shfl_xor_sync(0xffffffffu, d1, o);
        d2 += __shfl_xor_sync(0xffffffffu, d2, o);
        d3 += __shfl_xor_sync(0xffffffffu, d3, o);
    }
    float s0 = g_cnorm[cd.x] - 2.0f * d0;
    float s1 = g_cnorm[cd.y] - 2.0f * d1;
    float s2 = g_cnorm[cd.z] - 2.0f * d2;
    float s3 = g_cnorm[cd.w] - 2.0f * d3;

    float bs = s0; int bi = cd.x; float4 c = c0;
    if (s1 < bs || (s1 == bs && cd.y < bi)) { bs = s1; bi = cd.y; c = c1; }
    if (s2 < bs || (s2 == bs && cd.z < bi)) { bs = s2; bi = cd.z; c = c2; }
    if (s3 < bs || (s3 == bs && cd.w < bi)) { bs = s3; bi = cd.w; c = c3; }

    float dx = c.x - zv.x, dy = c.y - zv.y, dz = c.z - zv.z, dw = c.w - zv.w;
    float4 o4;
    o4.x = zv.x + dx; o4.y = zv.y + dy; o4.z = zv.z + dz; o4.w = zv.w + dw;
    ((float4*)(out + (size_t)t * DIM))[lane] = o4;

    float sq = dx * dx + dy * dy + dz * dz + dw * dw;
#pragma unroll
    for (int o = 16; o > 0; o >>= 1) sq += __shfl_xor_sync(0xffffffffu, sq, o);
    if (lane == 0) {
        wsq[warp] = sq;
        atomicAdd(&g_counts[bi], 1);
    }
    __syncthreads();
    if (threadIdx.x == 0) {
        double s = 0.0;
#pragma unroll
        for (int i = 0; i < 8; i++) s += (double)wsq[i];
        g_ssep[blockIdx.x] = s;
    }
}

/* ---------------- finalize commit_loss + perplexity ---------------- */
__global__ void k_final(float* __restrict__ out) {
    __shared__ double wd[8];
    __shared__ float wf[8];
    double sd = 0.0;
    for (int j = threadIdx.x; j < T_TOK / 8; j += 256) sd += g_ssep[j];
    float s = 0.0f;
    const float invT = 1.0f / (float)T_TOK;
    for (int i = threadIdx.x; i < KC; i += 256) {
        float e = (float)g_counts[i] * invT;
        s += e * logf(e + 1e-8f);
    }
#pragma unroll
    for (int o = 16; o > 0; o >>= 1) {
        sd += __shfl_down_sync(0xffffffffu, sd, o);
        s  += __shfl_down_sync(0xffffffffu, s, o);
    }
    if ((threadIdx.x & 31) == 0) { wd[threadIdx.x >> 5] = sd; wf[threadIdx.x >> 5] = s; }
    __syncthreads();
    if (threadIdx.x == 0) {
        double td = 0.0; float tf = 0.0f;
#pragma unroll
        for (int i = 0; i < 8; i++) { td += wd[i]; tf += wf[i]; }
        double mse = td / (double)((size_t)T_TOK * DIM);
        out[(size_t)T_TOK * DIM]     = (float)(1.25 * mse);
        out[(size_t)T_TOK * DIM + 1] = expf(-tf);
    }
}

extern "C" void kernel_launch(void* const* d_in, const int* in_sizes, int n_in,
                              void* d_out, int out_size) {
    const float* z   = (const float*)d_in[0];
    const float* emb = (const float*)d_in[1];
    const float* pw  = (const float*)d_in[2];
    const float* pb  = (const float*)d_in[3];
    float* out = (float*)d_out;

    cudaFuncSetAttribute(k_proj, cudaFuncAttributeMaxDynamicSharedMemorySize, SMEM_PROJ);
    cudaFuncSetAttribute(k_gemm, cudaFuncAttributeMaxDynamicSharedMemorySize, SMEM_GEMM);

    k_init<<<KC / 256, 256>>>();
    k_proj<<<KC / 128, 256, SMEM_PROJ>>>(emb, pw, pb);
    k_gemm<<<GRID_GEMM, 256, SMEM_GEMM>>>(z);
    k_rescore<<<T_TOK / 8, 256>>>(z, out);
    k_final<<<1, 256>>>(out);
}

// round 9
// speedup vs baseline: 2.1510x; 1.0438x over previous
#include <cuda_runtime.h>
#include <cuda_fp16.h>
#include <math.h>
#include <stdint.h>

#define T_TOK 32768
#define DIM   128
#define KC    8192
#define BM    128
#define NT    64
#define ITERS (KC / NT)          /* 128 */
#define GRID_GEMM (T_TOK / BM)   /* 256 */
#define TILE_BYTES 16384
#define SMEM_GEMM (2 * TILE_BYTES)
#define PAD 132
#define SMEM_PROJ (2 * 128 * PAD * 4)

/* ---------------- device scratch (no allocations) ---------------- */
__device__ __align__(16) unsigned char g_cbt[ITERS * TILE_BYTES]; /* 2MB fp16 B frags */
__device__ float  g_codebook[KC * DIM];
__device__ __align__(16) float g_cnorm[KC];
__device__ int4   g_cand[T_TOK];
__device__ int    g_counts[KC];
__device__ double g_ssep[T_TOK / 8];

__device__ __forceinline__ uint32_t smem_u32(const void* p) {
    uint32_t a;
    asm("{ .reg .u64 t; cvta.to.shared.u64 t, %1; cvt.u32.u64 %0, t; }"
        : "=r"(a) : "l"(p));
    return a;
}

#define CP16(dst, src) \
    asm volatile("cp.async.cg.shared.global [%0], [%1], 16;" :: "r"((uint32_t)(dst)), "l"(src))
#define CP_COMMIT() asm volatile("cp.async.commit_group;" ::: "memory")
#define CP_WAIT0()  asm volatile("cp.async.wait_group 0;"  ::: "memory")

#define MMA_F16(d, a, b0, b1) \
    asm volatile("mma.sync.aligned.m16n8k16.row.col.f32.f16.f16.f32 " \
                 "{%0,%1,%2,%3}, {%4,%5,%6,%7}, {%8,%9}, {%0,%1,%2,%3};" \
                 : "+f"((d)[0]), "+f"((d)[1]), "+f"((d)[2]), "+f"((d)[3]) \
                 : "r"((a)[0]), "r"((a)[1]), "r"((a)[2]), "r"((a)[3]), \
                   "r"(b0), "r"(b1))

/* pack candidate index into the low 13 mantissa bits of the score */
__device__ __forceinline__ float mangle(float s, int n) {
    return __uint_as_float((__float_as_uint(s) & 0xFFFFE000u) | (uint32_t)n);
}
/* insert x into ascending sorted quadruple (7 FMNMX, no predicates) */
#define PINS(p0, p1, p2, p3, x) do {                    \
    float _m0 = fmaxf(p0, x); p0 = fminf(p0, x);        \
    float _m1 = fmaxf(p1, _m0); p1 = fminf(p1, _m0);    \
    float _m2 = fmaxf(p2, _m1); p2 = fminf(p2, _m1);    \
    p3 = fminf(p3, _m2);                                \
} while (0)
#define PINIT __uint_as_float(0x7F000000u)

/* ---------------- zero counts ---------------- */
__global__ void k_init() {
    int i = blockIdx.x * blockDim.x + threadIdx.x;
    if (i < KC) g_counts[i] = 0;
}

/* ---------------- projection GEMM: C = emb @ W^T + b (128 codes/block) ----------------
   Emits fp32 codebook, cnorm, fp16 packed B fragments.
   Packed layout per 64-code tile (16KB): [nblk(8)][kblk(8)][lane(32)] x 8B,
   8B = {h(k), h(k+1), h(k+8), h(k+9)}, lane = nl*4 + ksub,
   n = tile*64 + nblk*8 + nl, k = kblk*16 + regsel*8 + ksub*2 + par */
__global__ __launch_bounds__(256, 1)
void k_proj(const float* __restrict__ emb,
            const float* __restrict__ pw,
            const float* __restrict__ pbias) {
    extern __shared__ float ps[];
    float* es = ps;
    float* wsm = ps + 128 * PAD;
    const int tid = threadIdx.x;
    const int tx = tid & 15, ty = tid >> 4;
    const int c0 = blockIdx.x * 128;

#pragma unroll
    for (int i = 0; i < 16; i++) {
        int f = tid + i * 256;
        int row = f >> 5;
        int c4 = f & 31;
        int sw = (((row >> 2) ^ (c4 & 7)) << 2) | (row & 3);
        float4 v = *((const float4*)(emb + (size_t)(c0 + row) * DIM) + c4);
        es[(4 * c4 + 0) * PAD + sw] = v.x;
        es[(4 * c4 + 1) * PAD + sw] = v.y;
        es[(4 * c4 + 2) * PAD + sw] = v.z;
        es[(4 * c4 + 3) * PAD + sw] = v.w;
        float4 w = *((const float4*)(pw + (size_t)row * DIM) + c4);
        wsm[(4 * c4 + 0) * PAD + sw] = w.x;
        wsm[(4 * c4 + 1) * PAD + sw] = w.y;
        wsm[(4 * c4 + 2) * PAD + sw] = w.z;
        wsm[(4 * c4 + 3) * PAD + sw] = w.w;
    }
    __syncthreads();

    float acc[8][8];
#pragma unroll
    for (int im = 0; im < 8; im++)
#pragma unroll
        for (int jn = 0; jn < 8; jn++) acc[im][jn] = 0.0f;

#pragma unroll 4
    for (int k = 0; k < 128; k++) {
        int s = (k >> 2) & 7;
        const float* er = es + k * PAD;
        const float* wr = wsm + k * PAD;
        float4 a0 = *(const float4*)(er + ((ty ^ s) << 2));
        float4 a1 = *(const float4*)(er + 64 + ((ty ^ s) << 2));
        float4 b0 = *(const float4*)(wr + ((tx ^ s) << 2));
        float4 b1 = *(const float4*)(wr + 64 + ((tx ^ s) << 2));
        float a[8] = {a0.x, a0.y, a0.z, a0.w, a1.x, a1.y, a1.z, a1.w};
        float b[8] = {b0.x, b0.y, b0.z, b0.w, b1.x, b1.y, b1.z, b1.w};
#pragma unroll
        for (int im = 0; im < 8; im++)
#pragma unroll
            for (int jn = 0; jn < 8; jn++)
                acc[im][jn] = fmaf(a[im], b[jn], acc[im][jn]);
    }

    float cnp[8];
#pragma unroll
    for (int im = 0; im < 8; im++) cnp[im] = 0.0f;

#pragma unroll
    for (int im = 0; im < 8; im++) {
        int cl = (im < 4) ? (ty * 4 + im) : (64 + ty * 4 + im - 4);
        int cg = c0 + cl;
        int tile = cg >> 6, nblk = (cg >> 3) & 7, nl = cg & 7;
#pragma unroll
        for (int jn = 0; jn < 8; jn++) {
            int d = (jn < 4) ? (tx * 4 + jn) : (64 + tx * 4 + jn - 4);
            float val = acc[im][jn] + pbias[d];
            g_codebook[(size_t)cg * DIM + d] = val;
            cnp[im] = fmaf(val, val, cnp[im]);
            int kblk = d >> 4, kin = d & 15;
            int regsel = kin >> 3, ksub = (kin & 7) >> 1, par = kin & 1;
            int lane = nl * 4 + ksub;
            size_t off = (size_t)tile * TILE_BYTES + nblk * 2048 + kblk * 256
                       + lane * 8 + regsel * 4 + par * 2;
            *(__half*)(g_cbt + off) = __float2half_rn(val);
        }
    }
#pragma unroll
    for (int im = 0; im < 8; im++) {
#pragma unroll
        for (int o = 8; o > 0; o >>= 1)
            cnp[im] += __shfl_xor_sync(0xffffffffu, cnp[im], o, 16);
    }
    if (tx == 0) {
#pragma unroll
        for (int im = 0; im < 8; im++) {
            int cl = (im < 4) ? (ty * 4 + im) : (64 + ty * 4 + im - 4);
            g_cnorm[c0 + cl] = cnp[im];
        }
    }
}

/* ---------------- fused fp16 HMMA distance GEMM + packed top-4 argmin ---------------- */
__global__ __launch_bounds__(256, 2)
void k_gemm(const float* __restrict__ z) {
    extern __shared__ unsigned char smem[];
    const uint32_t sb = smem_u32(smem);
    const int tid = threadIdx.x;
    const int lane = tid & 31;
    const int warp = tid >> 5;
    const int r = lane >> 2;
    const int cc = lane & 3;
    const int m0 = blockIdx.x * BM;

    /* prefetch B tile 0 */
#pragma unroll
    for (int j = 0; j < 4; j++) {
        uint32_t off = (uint32_t)(tid + j * 256) * 16;
        CP16(sb + off, g_cbt + off);
    }
    CP_COMMIT();

    /* A fragments (fp16) in registers */
    uint32_t A[8][4];
    {
        const float* z0 = z + (size_t)(m0 + warp * 16 + r) * DIM;
#pragma unroll
        for (int kb = 0; kb < 8; kb++) {
#pragma unroll
            for (int q = 0; q < 4; q++) {
                const float* src = z0 + ((q & 1) ? 8 * DIM : 0) + kb * 16 + (q >> 1) * 8 + cc * 2;
                float2 v = *(const float2*)src;
                __half2 hh = __floats2half2_rn(v.x, v.y);
                A[kb][q] = *(uint32_t*)&hh;
            }
        }
    }

    /* cnorm prefetch buffer for iter 0 */
    float2 cnbuf[8];
#pragma unroll
    for (int nb = 0; nb < 8; nb++)
        cnbuf[nb] = *(const float2*)(g_cnorm + nb * 8 + cc * 2);

    /* packed top-4 (index in low 13 mantissa bits), rows a and b */
    float pa0 = PINIT, pa1 = PINIT, pa2 = PINIT, pa3 = PINIT;
    float pb0 = PINIT, pb1 = PINIT, pb2 = PINIT, pb3 = PINIT;

    for (int i = 0; i < ITERS; i++) {
        CP_WAIT0();
        __syncthreads();
        if (i + 1 < ITERS) {
            const unsigned char* src = g_cbt + (size_t)(i + 1) * TILE_BYTES;
            uint32_t dst = sb + ((i + 1) & 1) * TILE_BYTES;
#pragma unroll
            for (int j = 0; j < 4; j++) {
                uint32_t off = (uint32_t)(tid + j * 256) * 16;
                CP16(dst + off, src + off);
            }
            CP_COMMIT();
        }

        float acc[8][4];
#pragma unroll
        for (int nb = 0; nb < 8; nb++)
#pragma unroll
            for (int q = 0; q < 4; q++) acc[nb][q] = 0.0f;

        const uint32_t bbase = sb + (i & 1) * TILE_BYTES + lane * 8;
#pragma unroll
        for (int kb = 0; kb < 8; kb++) {
#pragma unroll
            for (int nb = 0; nb < 8; nb++) {
                uint32_t b0, b1;
                asm volatile("ld.shared.v2.b32 {%0,%1},[%2];"
                             : "=r"(b0), "=r"(b1) : "r"(bbase + nb * 2048 + kb * 256));
                MMA_F16(acc[nb], A[kb], b0, b1);
            }
        }

        const int n0i = i * 64;
#pragma unroll
        for (int nb = 0; nb < 8; nb++) {
            int n = n0i + nb * 8 + cc * 2;
            float2 cn = cnbuf[nb];
            float s0 = mangle(fmaf(-2.0f, acc[nb][0], cn.x), n);
            float s1 = mangle(fmaf(-2.0f, acc[nb][1], cn.y), n + 1);
            float s2 = mangle(fmaf(-2.0f, acc[nb][2], cn.x), n);
            float s3 = mangle(fmaf(-2.0f, acc[nb][3], cn.y), n + 1);
            PINS(pa0, pa1, pa2, pa3, s0);
            PINS(pa0, pa1, pa2, pa3, s1);
            PINS(pb0, pb1, pb2, pb3, s2);
            PINS(pb0, pb1, pb2, pb3, s3);
        }
        /* prefetch next iteration's cnorms (latency hides under next MMA block) */
        if (i + 1 < ITERS) {
            const float* cnn = g_cnorm + (i + 1) * 64 + cc * 2;
#pragma unroll
            for (int nb = 0; nb < 8; nb++)
                cnbuf[nb] = *(const float2*)(cnn + nb * 8);
        }
    }

    /* merge packed top-4 across the 4 cc lanes */
#pragma unroll
    for (int off = 1; off <= 2; off <<= 1) {
        float w0 = __shfl_xor_sync(0xffffffffu, pa0, off);
        float w1 = __shfl_xor_sync(0xffffffffu, pa1, off);
        float w2 = __shfl_xor_sync(0xffffffffu, pa2, off);
        float w3 = __shfl_xor_sync(0xffffffffu, pa3, off);
        PINS(pa0, pa1, pa2, pa3, w0);
        PINS(pa0, pa1, pa2, pa3, w1);
        PINS(pa0, pa1, pa2, pa3, w2);
        PINS(pa0, pa1, pa2, pa3, w3);
        w0 = __shfl_xor_sync(0xffffffffu, pb0, off);
        w1 = __shfl_xor_sync(0xffffffffu, pb1, off);
        w2 = __shfl_xor_sync(0xffffffffu, pb2, off);
        w3 = __shfl_xor_sync(0xffffffffu, pb3, off);
        PINS(pb0, pb1, pb2, pb3, w0);
        PINS(pb0, pb1, pb2, pb3, w1);
        PINS(pb0, pb1, pb2, pb3, w2);
        PINS(pb0, pb1, pb2, pb3, w3);
    }
    if (cc == 0) {
        int tok = m0 + warp * 16 + r;
        g_cand[tok] = make_int4((int)(__float_as_uint(pa0) & 0x1FFFu),
                                (int)(__float_as_uint(pa1) & 0x1FFFu),
                                (int)(__float_as_uint(pa2) & 0x1FFFu),
                                (int)(__float_as_uint(pa3) & 0x1FFFu));
        g_cand[tok + 8] = make_int4((int)(__float_as_uint(pb0) & 0x1FFFu),
                                    (int)(__float_as_uint(pb1) & 0x1FFFu),
                                    (int)(__float_as_uint(pb2) & 0x1FFFu),
                                    (int)(__float_as_uint(pb3) & 0x1FFFu));
    }
}

/* ---------------- exact fp32 rescore of top-4 + gather + loss partials ---------------- */
__global__ __launch_bounds__(256)
void k_rescore(const float* __restrict__ z, float* __restrict__ out) {
    __shared__ float wsq[8];
    const int lane = threadIdx.x & 31;
    const int warp = threadIdx.x >> 5;
    const int t = blockIdx.x * 8 + warp;

    int4 cd = g_cand[t];
    float4 zv = ((const float4*)(z + (size_t)t * DIM))[lane];
    float4 c0 = ((const float4*)(g_codebook + (size_t)cd.x * DIM))[lane];
    float4 c1 = ((const float4*)(g_codebook + (size_t)cd.y * DIM))[lane];
    float4 c2 = ((const float4*)(g_codebook + (size_t)cd.z * DIM))[lane];
    float4 c3 = ((const float4*)(g_codebook + (size_t)cd.w * DIM))[lane];
    float d0 = zv.x * c0.x + zv.y * c0.y + zv.z * c0.z + zv.w * c0.w;
    float d1 = zv.x * c1.x + zv.y * c1.y + zv.z * c1.z + zv.w * c1.w;
    float d2 = zv.x * c2.x + zv.y * c2.y + zv.z * c2.z + zv.w * c2.w;
    float d3 = zv.x * c3.x + zv.y * c3.y + zv.z * c3.z + zv.w * c3.w;
#pragma unroll
    for (int o = 16; o > 0; o >>= 1) {
        d0 += __shfl_xor_sync(0xffffffffu, d0, o);
        d1 += __shfl_xor_sync(0xffffffffu, d1, o);
        d2 += __shfl_xor_sync(0xffffffffu, d2, o);
        d3 += __shfl_xor_sync(0xffffffffu, d3, o);
    }
    float s0 = g_cnorm[cd.x] - 2.0f * d0;
    float s1 = g_cnorm[cd.y] - 2.0f * d1;
    float s2 = g_cnorm[cd.z] - 2.0f * d2;
    float s3 = g_cnorm[cd.w] - 2.0f * d3;

    float bs = s0; int bi = cd.x; float4 c = c0;
    if (s1 < bs || (s1 == bs && cd.y < bi)) { bs = s1; bi = cd.y; c = c1; }
    if (s2 < bs || (s2 == bs && cd.z < bi)) { bs = s2; bi = cd.z; c = c2; }
    if (s3 < bs || (s3 == bs && cd.w < bi)) { bs = s3; bi = cd.w; c = c3; }

    float dx = c.x - zv.x, dy = c.y - zv.y, dz = c.z - zv.z, dw = c.w - zv.w;
    float4 o4;
    o4.x = zv.x + dx; o4.y = zv.y + dy; o4.z = zv.z + dz; o4.w = zv.w + dw;
    ((float4*)(out + (size_t)t * DIM))[lane] = o4;

    float sq = dx * dx + dy * dy + dz * dz + dw * dw;
#pragma unroll
    for (int o = 16; o > 0; o >>= 1) sq += __shfl_xor_sync(0xffffffffu, sq, o);
    if (lane == 0) {
        wsq[warp] = sq;
        atomicAdd(&g_counts[bi], 1);
    }
    __syncthreads();
    if (threadIdx.x == 0) {
        double s = 0.0;
#pragma unroll
        for (int i = 0; i < 8; i++) s += (double)wsq[i];
        g_ssep[blockIdx.x] = s;
    }
}

/* ---------------- finalize commit_loss + perplexity ---------------- */
__global__ void k_final(float* __restrict__ out) {
    __shared__ double wd[8];
    __shared__ float wf[8];
    double sd = 0.0;
    for (int j = threadIdx.x; j < T_TOK / 8; j += 256) sd += g_ssep[j];
    float s = 0.0f;
    const float invT = 1.0f / (float)T_TOK;
    for (int i = threadIdx.x; i < KC; i += 256) {
        float e = (float)g_counts[i] * invT;
        s += e * logf(e + 1e-8f);
    }
#pragma unroll
    for (int o = 16; o > 0; o >>= 1) {
        sd += __shfl_down_sync(0xffffffffu, sd, o);
        s  += __shfl_down_sync(0xffffffffu, s, o);
    }
    if ((threadIdx.x & 31) == 0) { wd[threadIdx.x >> 5] = sd; wf[threadIdx.x >> 5] = s; }
    __syncthreads();
    if (threadIdx.x == 0) {
        double td = 0.0; float tf = 0.0f;
#pragma unroll
        for (int i = 0; i < 8; i++) { td += wd[i]; tf += wf[i]; }
        double mse = td / (double)((size_t)T_TOK * DIM);
        out[(size_t)T_TOK * DIM]     = (float)(1.25 * mse);
        out[(size_t)T_TOK * DIM + 1] = expf(-tf);
    }
}

extern "C" void kernel_launch(void* const* d_in, const int* in_sizes, int n_in,
                              void* d_out, int out_size) {
    const float* z   = (const float*)d_in[0];
    const float* emb = (const float*)d_in[1];
    const float* pw  = (const float*)d_in[2];
    const float* pb  = (const float*)d_in[3];
    float* out = (float*)d_out;

    cudaFuncSetAttribute(k_proj, cudaFuncAttributeMaxDynamicSharedMemorySize, SMEM_PROJ);
    cudaFuncSetAttribute(k_gemm, cudaFuncAttributeMaxDynamicSharedMemorySize, SMEM_GEMM);

    k_init<<<KC / 256, 256>>>();
    k_proj<<<KC / 128, 256, SMEM_PROJ>>>(emb, pw, pb);
    k_gemm<<<GRID_GEMM, 256, SMEM_GEMM>>>(z);
    k_rescore<<<T_TOK / 8, 256>>>(z, out);
    k_final<<<1, 256>>>(out);
}

// round 10
// speedup vs baseline: 2.1912x; 1.0187x over previous
#include <cuda_runtime.h>
#include <cuda_fp16.h>
#include <math.h>
#include <stdint.h>

#define T_TOK 32768
#define DIM   128
#define KC    8192
#define BM    128
#define NT    64
#define ITERS (KC / NT)          /* 128 */
#define GRID_GEMM (T_TOK / BM)   /* 256 */
#define TILE_BYTES 16384
#define SMEM_GEMM (3 * TILE_BYTES)   /* 48KB: 3-deep ring */
#define PAD 132
#define SMEM_PROJ (2 * 128 * PAD * 4)

/* ---------------- device scratch (no allocations) ---------------- */
__device__ __align__(16) unsigned char g_cbt[ITERS * TILE_BYTES]; /* 2MB fp16 B frags */
__device__ float  g_codebook[KC * DIM];
__device__ __align__(16) float g_cnorm[KC];
__device__ int4   g_cand[T_TOK];
__device__ int    g_counts[KC];
__device__ double g_ssep[T_TOK / 8];

__device__ __forceinline__ uint32_t smem_u32(const void* p) {
    uint32_t a;
    asm("{ .reg .u64 t; cvta.to.shared.u64 t, %1; cvt.u32.u64 %0, t; }"
        : "=r"(a) : "l"(p));
    return a;
}

#define CP16(dst, src) \
    asm volatile("cp.async.cg.shared.global [%0], [%1], 16;" :: "r"((uint32_t)(dst)), "l"(src))
#define CP_COMMIT() asm volatile("cp.async.commit_group;" ::: "memory")
#define CP_WAIT1()  asm volatile("cp.async.wait_group 1;"  ::: "memory")

#define MMA_F16(d, a, b0, b1) \
    asm volatile("mma.sync.aligned.m16n8k16.row.col.f32.f16.f16.f32 " \
                 "{%0,%1,%2,%3}, {%4,%5,%6,%7}, {%8,%9}, {%0,%1,%2,%3};" \
                 : "+f"((d)[0]), "+f"((d)[1]), "+f"((d)[2]), "+f"((d)[3]) \
                 : "r"((a)[0]), "r"((a)[1]), "r"((a)[2]), "r"((a)[3]), \
                   "r"(b0), "r"(b1))

#define INS4(tv0, tv1, tv2, tv3, ti0, ti1, ti2, ti3, v, n) do {               \
    if ((v) < (tv3)) {                                                        \
        if ((v) < (tv2)) {                                                    \
            tv3 = tv2; ti3 = ti2;                                             \
            if ((v) < (tv1)) {                                                \
                tv2 = tv1; ti2 = ti1;                                         \
                if ((v) < (tv0)) { tv1 = tv0; ti1 = ti0; tv0 = (v); ti0 = (n); } \
                else             { tv1 = (v); ti1 = (n); }                    \
            } else { tv2 = (v); ti2 = (n); }                                  \
        } else { tv3 = (v); ti3 = (n); }                                      \
    }                                                                         \
} while (0)

/* ---------------- projection GEMM: C = emb @ W^T + b (128 codes/block) ----------------
   Emits fp32 codebook, cnorm, fp16 packed B fragments; also zeroes g_counts.
   Packed layout per 64-code tile (16KB): [nblk(8)][kblk(8)][lane(32)] x 8B,
   8B = {h(k), h(k+1), h(k+8), h(k+9)}, lane = nl*4 + ksub,
   n = tile*64 + nblk*8 + nl, k = kblk*16 + regsel*8 + ksub*2 + par */
__global__ __launch_bounds__(256, 1)
void k_proj(const float* __restrict__ emb,
            const float* __restrict__ pw,
            const float* __restrict__ pbias) {
    extern __shared__ float ps[];
    float* es = ps;
    float* wsm = ps + 128 * PAD;
    const int tid = threadIdx.x;
    const int tx = tid & 15, ty = tid >> 4;
    const int c0 = blockIdx.x * 128;

    if (tid < 128) g_counts[c0 + tid] = 0;   /* fold k_init in (64 blocks x 128) */

#pragma unroll
    for (int i = 0; i < 16; i++) {
        int f = tid + i * 256;
        int row = f >> 5;
        int c4 = f & 31;
        int sw = (((row >> 2) ^ (c4 & 7)) << 2) | (row & 3);
        float4 v = *((const float4*)(emb + (size_t)(c0 + row) * DIM) + c4);
        es[(4 * c4 + 0) * PAD + sw] = v.x;
        es[(4 * c4 + 1) * PAD + sw] = v.y;
        es[(4 * c4 + 2) * PAD + sw] = v.z;
        es[(4 * c4 + 3) * PAD + sw] = v.w;
        float4 w = *((const float4*)(pw + (size_t)row * DIM) + c4);
        wsm[(4 * c4 + 0) * PAD + sw] = w.x;
        wsm[(4 * c4 + 1) * PAD + sw] = w.y;
        wsm[(4 * c4 + 2) * PAD + sw] = w.z;
        wsm[(4 * c4 + 3) * PAD + sw] = w.w;
    }
    __syncthreads();

    float acc[8][8];
#pragma unroll
    for (int im = 0; im < 8; im++)
#pragma unroll
        for (int jn = 0; jn < 8; jn++) acc[im][jn] = 0.0f;

#pragma unroll 4
    for (int k = 0; k < 128; k++) {
        int s = (k >> 2) & 7;
        const float* er = es + k * PAD;
        const float* wr = wsm + k * PAD;
        float4 a0 = *(const float4*)(er + ((ty ^ s) << 2));
        float4 a1 = *(const float4*)(er + 64 + ((ty ^ s) << 2));
        float4 b0 = *(const float4*)(wr + ((tx ^ s) << 2));
        float4 b1 = *(const float4*)(wr + 64 + ((tx ^ s) << 2));
        float a[8] = {a0.x, a0.y, a0.z, a0.w, a1.x, a1.y, a1.z, a1.w};
        float b[8] = {b0.x, b0.y, b0.z, b0.w, b1.x, b1.y, b1.z, b1.w};
#pragma unroll
        for (int im = 0; im < 8; im++)
#pragma unroll
            for (int jn = 0; jn < 8; jn++)
                acc[im][jn] = fmaf(a[im], b[jn], acc[im][jn]);
    }

    float cnp[8];
#pragma unroll
    for (int im = 0; im < 8; im++) cnp[im] = 0.0f;

#pragma unroll
    for (int im = 0; im < 8; im++) {
        int cl = (im < 4) ? (ty * 4 + im) : (64 + ty * 4 + im - 4);
        int cg = c0 + cl;
        int tile = cg >> 6, nblk = (cg >> 3) & 7, nl = cg & 7;
#pragma unroll
        for (int jn = 0; jn < 8; jn++) {
            int d = (jn < 4) ? (tx * 4 + jn) : (64 + tx * 4 + jn - 4);
            float val = acc[im][jn] + pbias[d];
            g_codebook[(size_t)cg * DIM + d] = val;
            cnp[im] = fmaf(val, val, cnp[im]);
            int kblk = d >> 4, kin = d & 15;
            int regsel = kin >> 3, ksub = (kin & 7) >> 1, par = kin & 1;
            int lane = nl * 4 + ksub;
            size_t off = (size_t)tile * TILE_BYTES + nblk * 2048 + kblk * 256
                       + lane * 8 + regsel * 4 + par * 2;
            *(__half*)(g_cbt + off) = __float2half_rn(val);
        }
    }
#pragma unroll
    for (int im = 0; im < 8; im++) {
#pragma unroll
        for (int o = 8; o > 0; o >>= 1)
            cnp[im] += __shfl_xor_sync(0xffffffffu, cnp[im], o, 16);
    }
    if (tx == 0) {
#pragma unroll
        for (int im = 0; im < 8; im++) {
            int cl = (im < 4) ? (ty * 4 + im) : (64 + ty * 4 + im - 4);
            g_cnorm[c0 + cl] = cnp[im];
        }
    }
}

/* ---------------- fused fp16 HMMA distance GEMM + top-4 argmin (3-deep ring) ---------------- */
__global__ __launch_bounds__(256, 2)
void k_gemm(const float* __restrict__ z) {
    extern __shared__ unsigned char smem[];
    const uint32_t sb = smem_u32(smem);
    const int tid = threadIdx.x;
    const int lane = tid & 31;
    const int warp = tid >> 5;
    const int r = lane >> 2;
    const int cc = lane & 3;
    const int m0 = blockIdx.x * BM;

    /* prologue: prefetch B tiles 0 and 1 into ring slots 0,1 */
#pragma unroll
    for (int t = 0; t < 2; t++) {
        const unsigned char* src = g_cbt + (size_t)t * TILE_BYTES;
        uint32_t dst = sb + t * TILE_BYTES;
#pragma unroll
        for (int j = 0; j < 4; j++) {
            uint32_t off = (uint32_t)(tid + j * 256) * 16;
            CP16(dst + off, src + off);
        }
        CP_COMMIT();
    }

    /* A fragments (fp16) in registers */
    uint32_t A[8][4];
    {
        const float* z0 = z + (size_t)(m0 + warp * 16 + r) * DIM;
#pragma unroll
        for (int kb = 0; kb < 8; kb++) {
#pragma unroll
            for (int q = 0; q < 4; q++) {
                const float* src = z0 + ((q & 1) ? 8 * DIM : 0) + kb * 16 + (q >> 1) * 8 + cc * 2;
                float2 v = *(const float2*)src;
                __half2 hh = __floats2half2_rn(v.x, v.y);
                A[kb][q] = *(uint32_t*)&hh;
            }
        }
    }

    float av0 = 3.4e38f, av1 = 3.4e38f, av2 = 3.4e38f, av3 = 3.4e38f;
    float bv0 = 3.4e38f, bv1 = 3.4e38f, bv2 = 3.4e38f, bv3 = 3.4e38f;
    int ai0 = 0, ai1 = 0, ai2 = 0, ai3 = 0;
    int bi0 = 0, bi1 = 0, bi2 = 0, bi3 = 0;

    int buf = 0, nbuf = 2;     /* compute slot, next-fill slot */
    for (int i = 0; i < ITERS; i++) {
        CP_WAIT1();            /* tile i resident; tile i+1 copy may still fly */
        __syncthreads();
        if (i + 2 < ITERS) {   /* refill slot vacated two iters ago */
            const unsigned char* src = g_cbt + (size_t)(i + 2) * TILE_BYTES;
            uint32_t dst = sb + nbuf * TILE_BYTES;
#pragma unroll
            for (int j = 0; j < 4; j++) {
                uint32_t off = (uint32_t)(tid + j * 256) * 16;
                CP16(dst + off, src + off);
            }
        }
        CP_COMMIT();

        float acc[8][4];
#pragma unroll
        for (int nb = 0; nb < 8; nb++)
#pragma unroll
            for (int q = 0; q < 4; q++) acc[nb][q] = 0.0f;

        const uint32_t bbase = sb + buf * TILE_BYTES + lane * 8;
#pragma unroll
        for (int kb = 0; kb < 8; kb++) {
#pragma unroll
            for (int nb = 0; nb < 8; nb++) {
                uint32_t b0, b1;
                asm volatile("ld.shared.v2.b32 {%0,%1},[%2];"
                             : "=r"(b0), "=r"(b1) : "r"(bbase + nb * 2048 + kb * 256));
                MMA_F16(acc[nb], A[kb], b0, b1);
            }
        }

        const int n0i = i * 64;
#pragma unroll
        for (int nb = 0; nb < 8; nb++) {
            int n = n0i + nb * 8 + cc * 2;
            float2 cn = *(const float2*)(g_cnorm + n);
            float s0 = fmaf(-2.0f, acc[nb][0], cn.x);
            float s1 = fmaf(-2.0f, acc[nb][1], cn.y);
            float s2 = fmaf(-2.0f, acc[nb][2], cn.x);
            float s3 = fmaf(-2.0f, acc[nb][3], cn.y);
            INS4(av0, av1, av2, av3, ai0, ai1, ai2, ai3, s0, n);
            INS4(av0, av1, av2, av3, ai0, ai1, ai2, ai3, s1, n + 1);
            INS4(bv0, bv1, bv2, bv3, bi0, bi1, bi2, bi3, s2, n);
            INS4(bv0, bv1, bv2, bv3, bi0, bi1, bi2, bi3, s3, n + 1);
        }
        buf = (buf == 2) ? 0 : buf + 1;
        nbuf = (nbuf == 2) ? 0 : nbuf + 1;
    }

    /* merge top-4 across the 4 cc lanes */
#pragma unroll
    for (int off = 1; off <= 2; off <<= 1) {
        float wa0 = __shfl_xor_sync(0xffffffffu, av0, off);
        float wa1 = __shfl_xor_sync(0xffffffffu, av1, off);
        float wa2 = __shfl_xor_sync(0xffffffffu, av2, off);
        float wa3 = __shfl_xor_sync(0xffffffffu, av3, off);
        int ja0 = __shfl_xor_sync(0xffffffffu, ai0, off);
        int ja1 = __shfl_xor_sync(0xffffffffu, ai1, off);
        int ja2 = __shfl_xor_sync(0xffffffffu, ai2, off);
        int ja3 = __shfl_xor_sync(0xffffffffu, ai3, off);
        float wb0 = __shfl_xor_sync(0xffffffffu, bv0, off);
        float wb1 = __shfl_xor_sync(0xffffffffu, bv1, off);
        float wb2 = __shfl_xor_sync(0xffffffffu, bv2, off);
        float wb3 = __shfl_xor_sync(0xffffffffu, bv3, off);
        int jb0 = __shfl_xor_sync(0xffffffffu, bi0, off);
        int jb1 = __shfl_xor_sync(0xffffffffu, bi1, off);
        int jb2 = __shfl_xor_sync(0xffffffffu, bi2, off);
        int jb3 = __shfl_xor_sync(0xffffffffu, bi3, off);
        INS4(av0, av1, av2, av3, ai0, ai1, ai2, ai3, wa0, ja0);
        INS4(av0, av1, av2, av3, ai0, ai1, ai2, ai3, wa1, ja1);
        INS4(av0, av1, av2, av3, ai0, ai1, ai2, ai3, wa2, ja2);
        INS4(av0, av1, av2, av3, ai0, ai1, ai2, ai3, wa3, ja3);
        INS4(bv0, bv1, bv2, bv3, bi0, bi1, bi2, bi3, wb0, jb0);
        INS4(bv0, bv1, bv2, bv3, bi0, bi1, bi2, bi3, wb1, jb1);
        INS4(bv0, bv1, bv2, bv3, bi0, bi1, bi2, bi3, wb2, jb2);
        INS4(bv0, bv1, bv2, bv3, bi0, bi1, bi2, bi3, wb3, jb3);
    }
    if (cc == 0) {
        int tok = m0 + warp * 16 + r;
        g_cand[tok]     = make_int4(ai0, ai1, ai2, ai3);
        g_cand[tok + 8] = make_int4(bi0, bi1, bi2, bi3);
    }
}

/* ---------------- exact fp32 rescore of top-4 + gather + loss partials ---------------- */
__global__ __launch_bounds__(256)
void k_rescore(const float* __restrict__ z, float* __restrict__ out) {
    __shared__ float wsq[8];
    const int lane = threadIdx.x & 31;
    const int warp = threadIdx.x >> 5;
    const int t = blockIdx.x * 8 + warp;

    int4 cd = g_cand[t];
    float4 zv = ((const float4*)(z + (size_t)t * DIM))[lane];
    float4 c0 = ((const float4*)(g_codebook + (size_t)cd.x * DIM))[lane];
    float4 c1 = ((const float4*)(g_codebook + (size_t)cd.y * DIM))[lane];
    float4 c2 = ((const float4*)(g_codebook + (size_t)cd.z * DIM))[lane];
    float4 c3 = ((const float4*)(g_codebook + (size_t)cd.w * DIM))[lane];
    float d0 = zv.x * c0.x + zv.y * c0.y + zv.z * c0.z + zv.w * c0.w;
    float d1 = zv.x * c1.x + zv.y * c1.y + zv.z * c1.z + zv.w * c1.w;
    float d2 = zv.x * c2.x + zv.y * c2.y + zv.z * c2.z + zv.w * c2.w;
    float d3 = zv.x * c3.x + zv.y * c3.y + zv.z * c3.z + zv.w * c3.w;
#pragma unroll
    for (int o = 16; o > 0; o >>= 1) {
        d0 += __shfl_xor_sync(0xffffffffu, d0, o);
        d1 += __shfl_xor_sync(0xffffffffu, d1, o);
        d2 += __shfl_xor_sync(0xffffffffu, d2, o);
        d3 += __shfl_xor_sync(0xffffffffu, d3, o);
    }
    float s0 = g_cnorm[cd.x] - 2.0f * d0;
    float s1 = g_cnorm[cd.y] - 2.0f * d1;
    float s2 = g_cnorm[cd.z] - 2.0f * d2;
    float s3 = g_cnorm[cd.w] - 2.0f * d3;

    float bs = s0; int bi = cd.x; float4 c = c0;
    if (s1 < bs || (s1 == bs && cd.y < bi)) { bs = s1; bi = cd.y; c = c1; }
    if (s2 < bs || (s2 == bs && cd.z < bi)) { bs = s2; bi = cd.z; c = c2; }
    if (s3 < bs || (s3 == bs && cd.w < bi)) { bs = s3; bi = cd.w; c = c3; }

    float dx = c.x - zv.x, dy = c.y - zv.y, dz = c.z - zv.z, dw = c.w - zv.w;
    float4 o4;
    o4.x = zv.x + dx; o4.y = zv.y + dy; o4.z = zv.z + dz; o4.w = zv.w + dw;
    ((float4*)(out + (size_t)t * DIM))[lane] = o4;

    float sq = dx * dx + dy * dy + dz * dz + dw * dw;
#pragma unroll
    for (int o = 16; o > 0; o >>= 1) sq += __shfl_xor_sync(0xffffffffu, sq, o);
    if (lane == 0) {
        wsq[warp] = sq;
        atomicAdd(&g_counts[bi], 1);
    }
    __syncthreads();
    if (threadIdx.x == 0) {
        double s = 0.0;
#pragma unroll
        for (int i = 0; i < 8; i++) s += (double)wsq[i];
        g_ssep[blockIdx.x] = s;
    }
}

/* ---------------- finalize commit_loss + perplexity ---------------- */
__global__ void k_final(float* __restrict__ out) {
    __shared__ double wd[8];
    __shared__ float wf[8];
    double sd = 0.0;
    for (int j = threadIdx.x; j < T_TOK / 8; j += 256) sd += g_ssep[j];
    float s = 0.0f;
    const float invT = 1.0f / (float)T_TOK;
    for (int i = threadIdx.x; i < KC; i += 256) {
        float e = (float)g_counts[i] * invT;
        s += e * logf(e + 1e-8f);
    }
#pragma unroll
    for (int o = 16; o > 0; o >>= 1) {
        sd += __shfl_down_sync(0xffffffffu, sd, o);
        s  += __shfl_down_sync(0xffffffffu, s, o);
    }
    if ((threadIdx.x & 31) == 0) { wd[threadIdx.x >> 5] = sd; wf[threadIdx.x >> 5] = s; }
    __syncthreads();
    if (threadIdx.x == 0) {
        double td = 0.0; float tf = 0.0f;
#pragma unroll
        for (int i = 0; i < 8; i++) { td += wd[i]; tf += wf[i]; }
        double mse = td / (double)((size_t)T_TOK * DIM);
        out[(size_t)T_TOK * DIM]     = (float)(1.25 * mse);
        out[(size_t)T_TOK * DIM + 1] = expf(-tf);
    }
}

extern "C" void kernel_launch(void* const* d_in, const int* in_sizes, int n_in,
                              void* d_out, int out_size) {
    const float* z   = (const float*)d_in[0];
    const float* emb = (const float*)d_in[1];
    const float* pw  = (const float*)d_in[2];
    const float* pb  = (const float*)d_in[3];
    float* out = (float*)d_out;

    cudaFuncSetAttribute(k_proj, cudaFuncAttributeMaxDynamicSharedMemorySize, SMEM_PROJ);
    cudaFuncSetAttribute(k_gemm, cudaFuncAttributeMaxDynamicSharedMemorySize, SMEM_GEMM);

    k_proj<<<KC / 128, 256, SMEM_PROJ>>>(emb, pw, pb);
    k_gemm<<<GRID_GEMM, 256, SMEM_GEMM>>>(z);
    k_rescore<<<T_TOK / 8, 256>>>(z, out);
    k_final<<<1, 256>>>(out);
}

// round 11
// speedup vs baseline: 2.1996x; 1.0038x over previous
#include <cuda_runtime.h>
#include <cuda_fp16.h>
#include <math.h>
#include <stdint.h>

#define T_TOK 32768
#define DIM   128
#define KC    8192
#define BM    128
#define NT    64
#define ITERS (KC / NT)          /* 128 */
#define GRID_GEMM (T_TOK / BM)   /* 256 */
#define TILE_BYTES 16384
#define SMEM_GEMM (3 * TILE_BYTES)   /* 48KB: 3-deep ring */
#define PAD 132
#define SMEM_PROJ (2 * 128 * PAD * 4)

/* ---------------- device scratch (no allocations) ---------------- */
__device__ __align__(16) unsigned char g_cbt[ITERS * TILE_BYTES]; /* 2MB fp16 B frags */
__device__ float  g_codebook[KC * DIM];
__device__ __align__(16) float g_cnorm[KC];
__device__ int    g_counts[KC];
__device__ double g_ssep[GRID_GEMM];
__device__ unsigned int g_done;

__device__ __forceinline__ uint32_t smem_u32(const void* p) {
    uint32_t a;
    asm("{ .reg .u64 t; cvta.to.shared.u64 t, %1; cvt.u32.u64 %0, t; }"
        : "=r"(a) : "l"(p));
    return a;
}

#define CP16(dst, src) \
    asm volatile("cp.async.cg.shared.global [%0], [%1], 16;" :: "r"((uint32_t)(dst)), "l"(src))
#define CP_COMMIT() asm volatile("cp.async.commit_group;" ::: "memory")
#define CP_WAIT1()  asm volatile("cp.async.wait_group 1;"  ::: "memory")
#define CP_WAIT0()  asm volatile("cp.async.wait_group 0;"  ::: "memory")

#define MMA_F16(d, a, b0, b1) \
    asm volatile("mma.sync.aligned.m16n8k16.row.col.f32.f16.f16.f32 " \
                 "{%0,%1,%2,%3}, {%4,%5,%6,%7}, {%8,%9}, {%0,%1,%2,%3};" \
                 : "+f"((d)[0]), "+f"((d)[1]), "+f"((d)[2]), "+f"((d)[3]) \
                 : "r"((a)[0]), "r"((a)[1]), "r"((a)[2]), "r"((a)[3]), \
                   "r"(b0), "r"(b1))

#define INS4(tv0, tv1, tv2, tv3, ti0, ti1, ti2, ti3, v, n) do {               \
    if ((v) < (tv3)) {                                                        \
        if ((v) < (tv2)) {                                                    \
            tv3 = tv2; ti3 = ti2;                                             \
            if ((v) < (tv1)) {                                                \
                tv2 = tv1; ti2 = ti1;                                         \
                if ((v) < (tv0)) { tv1 = tv0; ti1 = ti0; tv0 = (v); ti0 = (n); } \
                else             { tv1 = (v); ti1 = (n); }                    \
            } else { tv2 = (v); ti2 = (n); }                                  \
        } else { tv3 = (v); ti3 = (n); }                                      \
    }                                                                         \
} while (0)

/* ---------------- projection GEMM: C = emb @ W^T + b (128 codes/block) ----------------
   Emits fp32 codebook, cnorm, fp16 packed B fragments; zeroes g_counts and g_done. */
__global__ __launch_bounds__(256, 1)
void k_proj(const float* __restrict__ emb,
            const float* __restrict__ pw,
            const float* __restrict__ pbias) {
    extern __shared__ float ps[];
    float* es = ps;
    float* wsm = ps + 128 * PAD;
    const int tid = threadIdx.x;
    const int tx = tid & 15, ty = tid >> 4;
    const int c0 = blockIdx.x * 128;

    if (tid < 128) g_counts[c0 + tid] = 0;
    if (blockIdx.x == 0 && tid == 0) g_done = 0;

#pragma unroll
    for (int i = 0; i < 16; i++) {
        int f = tid + i * 256;
        int row = f >> 5;
        int c4 = f & 31;
        int sw = (((row >> 2) ^ (c4 & 7)) << 2) | (row & 3);
        float4 v = *((const float4*)(emb + (size_t)(c0 + row) * DIM) + c4);
        es[(4 * c4 + 0) * PAD + sw] = v.x;
        es[(4 * c4 + 1) * PAD + sw] = v.y;
        es[(4 * c4 + 2) * PAD + sw] = v.z;
        es[(4 * c4 + 3) * PAD + sw] = v.w;
        float4 w = *((const float4*)(pw + (size_t)row * DIM) + c4);
        wsm[(4 * c4 + 0) * PAD + sw] = w.x;
        wsm[(4 * c4 + 1) * PAD + sw] = w.y;
        wsm[(4 * c4 + 2) * PAD + sw] = w.z;
        wsm[(4 * c4 + 3) * PAD + sw] = w.w;
    }
    __syncthreads();

    float acc[8][8];
#pragma unroll
    for (int im = 0; im < 8; im++)
#pragma unroll
        for (int jn = 0; jn < 8; jn++) acc[im][jn] = 0.0f;

#pragma unroll 4
    for (int k = 0; k < 128; k++) {
        int s = (k >> 2) & 7;
        const float* er = es + k * PAD;
        const float* wr = wsm + k * PAD;
        float4 a0 = *(const float4*)(er + ((ty ^ s) << 2));
        float4 a1 = *(const float4*)(er + 64 + ((ty ^ s) << 2));
        float4 b0 = *(const float4*)(wr + ((tx ^ s) << 2));
        float4 b1 = *(const float4*)(wr + 64 + ((tx ^ s) << 2));
        float a[8] = {a0.x, a0.y, a0.z, a0.w, a1.x, a1.y, a1.z, a1.w};
        float b[8] = {b0.x, b0.y, b0.z, b0.w, b1.x, b1.y, b1.z, b1.w};
#pragma unroll
        for (int im = 0; im < 8; im++)
#pragma unroll
            for (int jn = 0; jn < 8; jn++)
                acc[im][jn] = fmaf(a[im], b[jn], acc[im][jn]);
    }

    float cnp[8];
#pragma unroll
    for (int im = 0; im < 8; im++) cnp[im] = 0.0f;

#pragma unroll
    for (int im = 0; im < 8; im++) {
        int cl = (im < 4) ? (ty * 4 + im) : (64 + ty * 4 + im - 4);
        int cg = c0 + cl;
        int tile = cg >> 6, nblk = (cg >> 3) & 7, nl = cg & 7;
#pragma unroll
        for (int jn = 0; jn < 8; jn++) {
            int d = (jn < 4) ? (tx * 4 + jn) : (64 + tx * 4 + jn - 4);
            float val = acc[im][jn] + pbias[d];
            g_codebook[(size_t)cg * DIM + d] = val;
            cnp[im] = fmaf(val, val, cnp[im]);
            int kblk = d >> 4, kin = d & 15;
            int regsel = kin >> 3, ksub = (kin & 7) >> 1, par = kin & 1;
            int lane = nl * 4 + ksub;
            size_t off = (size_t)tile * TILE_BYTES + nblk * 2048 + kblk * 256
                       + lane * 8 + regsel * 4 + par * 2;
            *(__half*)(g_cbt + off) = __float2half_rn(val);
        }
    }
#pragma unroll
    for (int im = 0; im < 8; im++) {
#pragma unroll
        for (int o = 8; o > 0; o >>= 1)
            cnp[im] += __shfl_xor_sync(0xffffffffu, cnp[im], o, 16);
    }
    if (tx == 0) {
#pragma unroll
        for (int im = 0; im < 8; im++) {
            int cl = (im < 4) ? (ty * 4 + im) : (64 + ty * 4 + im - 4);
            g_cnorm[c0 + cl] = cnp[im];
        }
    }
}

/* ---------------- fused: fp16 HMMA GEMM + top-4 + exact rescore + loss/perplexity ---------------- */
__global__ __launch_bounds__(256, 2)
void k_gemm(const float* __restrict__ z, float* __restrict__ out) {
    extern __shared__ unsigned char smem[];
    const uint32_t sb = smem_u32(smem);
    const int tid = threadIdx.x;
    const int lane = tid & 31;
    const int warp = tid >> 5;
    const int r = lane >> 2;
    const int cc = lane & 3;
    const int m0 = blockIdx.x * BM;

    /* prologue: prefetch B tiles 0 and 1 into ring slots 0,1 */
#pragma unroll
    for (int t = 0; t < 2; t++) {
        const unsigned char* src = g_cbt + (size_t)t * TILE_BYTES;
        uint32_t dst = sb + t * TILE_BYTES;
#pragma unroll
        for (int j = 0; j < 4; j++) {
            uint32_t off = (uint32_t)(tid + j * 256) * 16;
            CP16(dst + off, src + off);
        }
        CP_COMMIT();
    }

    /* A fragments (fp16) in registers */
    uint32_t A[8][4];
    {
        const float* z0 = z + (size_t)(m0 + warp * 16 + r) * DIM;
#pragma unroll
        for (int kb = 0; kb < 8; kb++) {
#pragma unroll
            for (int q = 0; q < 4; q++) {
                const float* src = z0 + ((q & 1) ? 8 * DIM : 0) + kb * 16 + (q >> 1) * 8 + cc * 2;
                float2 v = *(const float2*)src;
                __half2 hh = __floats2half2_rn(v.x, v.y);
                A[kb][q] = *(uint32_t*)&hh;
            }
        }
    }

    float av0 = 3.4e38f, av1 = 3.4e38f, av2 = 3.4e38f, av3 = 3.4e38f;
    float bv0 = 3.4e38f, bv1 = 3.4e38f, bv2 = 3.4e38f, bv3 = 3.4e38f;
    int ai0 = 0, ai1 = 0, ai2 = 0, ai3 = 0;
    int bi0 = 0, bi1 = 0, bi2 = 0, bi3 = 0;

    int buf = 0, nbuf = 2;
    for (int i = 0; i < ITERS; i++) {
        CP_WAIT1();
        __syncthreads();
        if (i + 2 < ITERS) {
            const unsigned char* src = g_cbt + (size_t)(i + 2) * TILE_BYTES;
            uint32_t dst = sb + nbuf * TILE_BYTES;
#pragma unroll
            for (int j = 0; j < 4; j++) {
                uint32_t off = (uint32_t)(tid + j * 256) * 16;
                CP16(dst + off, src + off);
            }
        }
        CP_COMMIT();

        float acc[8][4];
#pragma unroll
        for (int nb = 0; nb < 8; nb++)
#pragma unroll
            for (int q = 0; q < 4; q++) acc[nb][q] = 0.0f;

        const uint32_t bbase = sb + buf * TILE_BYTES + lane * 8;
#pragma unroll
        for (int kb = 0; kb < 8; kb++) {
#pragma unroll
            for (int nb = 0; nb < 8; nb++) {
                uint32_t b0, b1;
                asm volatile("ld.shared.v2.b32 {%0,%1},[%2];"
                             : "=r"(b0), "=r"(b1) : "r"(bbase + nb * 2048 + kb * 256));
                MMA_F16(acc[nb], A[kb], b0, b1);
            }
        }

        const int n0i = i * 64;
#pragma unroll
        for (int nb = 0; nb < 8; nb++) {
            int n = n0i + nb * 8 + cc * 2;
            float2 cn = *(const float2*)(g_cnorm + n);
            float s0 = fmaf(-2.0f, acc[nb][0], cn.x);
            float s1 = fmaf(-2.0f, acc[nb][1], cn.y);
            float s2 = fmaf(-2.0f, acc[nb][2], cn.x);
            float s3 = fmaf(-2.0f, acc[nb][3], cn.y);
            INS4(av0, av1, av2, av3, ai0, ai1, ai2, ai3, s0, n);
            INS4(av0, av1, av2, av3, ai0, ai1, ai2, ai3, s1, n + 1);
            INS4(bv0, bv1, bv2, bv3, bi0, bi1, bi2, bi3, s2, n);
            INS4(bv0, bv1, bv2, bv3, bi0, bi1, bi2, bi3, s3, n + 1);
        }
        buf = (buf == 2) ? 0 : buf + 1;
        nbuf = (nbuf == 2) ? 0 : nbuf + 1;
    }

    /* merge top-4 across the 4 cc lanes */
#pragma unroll
    for (int off = 1; off <= 2; off <<= 1) {
        float wa0 = __shfl_xor_sync(0xffffffffu, av0, off);
        float wa1 = __shfl_xor_sync(0xffffffffu, av1, off);
        float wa2 = __shfl_xor_sync(0xffffffffu, av2, off);
        float wa3 = __shfl_xor_sync(0xffffffffu, av3, off);
        int ja0 = __shfl_xor_sync(0xffffffffu, ai0, off);
        int ja1 = __shfl_xor_sync(0xffffffffu, ai1, off);
        int ja2 = __shfl_xor_sync(0xffffffffu, ai2, off);
        int ja3 = __shfl_xor_sync(0xffffffffu, ai3, off);
        float wb0 = __shfl_xor_sync(0xffffffffu, bv0, off);
        float wb1 = __shfl_xor_sync(0xffffffffu, bv1, off);
        float wb2 = __shfl_xor_sync(0xffffffffu, bv2, off);
        float wb3 = __shfl_xor_sync(0xffffffffu, bv3, off);
        int jb0 = __shfl_xor_sync(0xffffffffu, bi0, off);
        int jb1 = __shfl_xor_sync(0xffffffffu, bi1, off);
        int jb2 = __shfl_xor_sync(0xffffffffu, bi2, off);
        int jb3 = __shfl_xor_sync(0xffffffffu, bi3, off);
        INS4(av0, av1, av2, av3, ai0, ai1, ai2, ai3, wa0, ja0);
        INS4(av0, av1, av2, av3, ai0, ai1, ai2, ai3, wa1, ja1);
        INS4(av0, av1, av2, av3, ai0, ai1, ai2, ai3, wa2, ja2);
        INS4(av0, av1, av2, av3, ai0, ai1, ai2, ai3, wa3, ja3);
        INS4(bv0, bv1, bv2, bv3, bi0, bi1, bi2, bi3, wb0, jb0);
        INS4(bv0, bv1, bv2, bv3, bi0, bi1, bi2, bi3, wb1, jb1);
        INS4(bv0, bv1, bv2, bv3, bi0, bi1, bi2, bi3, wb2, jb2);
        INS4(bv0, bv1, bv2, bv3, bi0, bi1, bi2, bi3, wb3, jb3);
    }

    /* ---- fused rescore: stash candidates in smem (ring is drained) ---- */
    CP_WAIT0();
    __syncthreads();
    int4*  scand = (int4*)smem;                 /* 128 x 16B = 2KB */
    float* swsq  = (float*)(smem + 2048);
    int*   sflag = (int*)(smem + 2048 + 32);
    if (cc == 0) {
        scand[warp * 16 + r]     = make_int4(ai0, ai1, ai2, ai3);
        scand[warp * 16 + r + 8] = make_int4(bi0, bi1, bi2, bi3);
    }
    __syncthreads();

    /* each warp rescores 16 tokens in exact fp32, writes z_q_st, accumulates SSE + counts */
    float warp_sq = 0.0f;
    for (int j = 0; j < 16; j++) {
        const int tl = warp * 16 + j;
        const int t = m0 + tl;
        int4 cd = scand[tl];
        float4 zv = ((const float4*)(z + (size_t)t * DIM))[lane];
        float4 c0 = ((const float4*)(g_codebook + (size_t)cd.x * DIM))[lane];
        float4 c1 = ((const float4*)(g_codebook + (size_t)cd.y * DIM))[lane];
        float4 c2 = ((const float4*)(g_codebook + (size_t)cd.z * DIM))[lane];
        float4 c3 = ((const float4*)(g_codebook + (size_t)cd.w * DIM))[lane];
        float d0 = zv.x * c0.x + zv.y * c0.y + zv.z * c0.z + zv.w * c0.w;
        float d1 = zv.x * c1.x + zv.y * c1.y + zv.z * c1.z + zv.w * c1.w;
        float d2 = zv.x * c2.x + zv.y * c2.y + zv.z * c2.z + zv.w * c2.w;
        float d3 = zv.x * c3.x + zv.y * c3.y + zv.z * c3.z + zv.w * c3.w;
#pragma unroll
        for (int o = 16; o > 0; o >>= 1) {
            d0 += __shfl_xor_sync(0xffffffffu, d0, o);
            d1 += __shfl_xor_sync(0xffffffffu, d1, o);
            d2 += __shfl_xor_sync(0xffffffffu, d2, o);
            d3 += __shfl_xor_sync(0xffffffffu, d3, o);
        }
        float s0 = g_cnorm[cd.x] - 2.0f * d0;
        float s1 = g_cnorm[cd.y] - 2.0f * d1;
        float s2 = g_cnorm[cd.z] - 2.0f * d2;
        float s3 = g_cnorm[cd.w] - 2.0f * d3;

        float bs = s0; int bi = cd.x; float4 c = c0;
        if (s1 < bs || (s1 == bs && cd.y < bi)) { bs = s1; bi = cd.y; c = c1; }
        if (s2 < bs || (s2 == bs && cd.z < bi)) { bs = s2; bi = cd.z; c = c2; }
        if (s3 < bs || (s3 == bs && cd.w < bi)) { bs = s3; bi = cd.w; c = c3; }

        float dx = c.x - zv.x, dy = c.y - zv.y, dz = c.z - zv.z, dw = c.w - zv.w;
        float4 o4;
        o4.x = zv.x + dx; o4.y = zv.y + dy; o4.z = zv.z + dz; o4.w = zv.w + dw;
        ((float4*)(out + (size_t)t * DIM))[lane] = o4;

        float sq = dx * dx + dy * dy + dz * dz + dw * dw;
#pragma unroll
        for (int o = 16; o > 0; o >>= 1) sq += __shfl_xor_sync(0xffffffffu, sq, o);
        warp_sq += sq;
        if (lane == 0) atomicAdd(&g_counts[bi], 1);
    }
    if (lane == 0) swsq[warp] = warp_sq;
    __syncthreads();
    if (tid == 0) {
        double s = 0.0;
#pragma unroll
        for (int i = 0; i < 8; i++) s += (double)swsq[i];
        g_ssep[blockIdx.x] = s;
        __threadfence();
        unsigned int t = atomicAdd(&g_done, 1u);
        *sflag = (t == GRID_GEMM - 1) ? 1 : 0;
    }
    __syncthreads();

    /* ---- last CTA computes commit_loss + perplexity ---- */
    if (*sflag) {
        __threadfence();
        __shared__ double wd[8];
        __shared__ float wf[8];
        double sd = g_ssep[tid];    /* exactly 256 partials, 256 threads */
        float s = 0.0f;
        const float invT = 1.0f / (float)T_TOK;
        for (int i = tid; i < KC; i += 256) {
            float e = (float)g_counts[i] * invT;
            s += e * logf(e + 1e-8f);
        }
#pragma unroll
        for (int o = 16; o > 0; o >>= 1) {
            sd += __shfl_down_sync(0xffffffffu, sd, o);
            s  += __shfl_down_sync(0xffffffffu, s, o);
        }
        if (lane == 0) { wd[warp] = sd; wf[warp] = s; }
        __syncthreads();
        if (tid == 0) {
            double td = 0.0; float tf = 0.0f;
#pragma unroll
            for (int i = 0; i < 8; i++) { td += wd[i]; tf += wf[i]; }
            double mse = td / (double)((size_t)T_TOK * DIM);
            out[(size_t)T_TOK * DIM]     = (float)(1.25 * mse);
            out[(size_t)T_TOK * DIM + 1] = expf(-tf);
        }
    }
}

extern "C" void kernel_launch(void* const* d_in, const int* in_sizes, int n_in,
                              void* d_out, int out_size) {
    const float* z   = (const float*)d_in[0];
    const float* emb = (const float*)d_in[1];
    const float* pw  = (const float*)d_in[2];
    const float* pb  = (const float*)d_in[3];
    float* out = (float*)d_out;

    cudaFuncSetAttribute(k_proj, cudaFuncAttributeMaxDynamicSharedMemorySize, SMEM_PROJ);
    cudaFuncSetAttribute(k_gemm, cudaFuncAttributeMaxDynamicSharedMemorySize, SMEM_GEMM);

    k_proj<<<KC / 128, 256, SMEM_PROJ>>>(emb, pw, pb);
    k_gemm<<<GRID_GEMM, 256, SMEM_GEMM>>>(z, out);
}